// round 1
// baseline (speedup 1.0000x reference)
#include <cuda_runtime.h>
#include <math.h>

// Problem constants (fixed by setup_inputs)
#define Bn   8
#define Sn   64
#define Cn   64
#define Hn   32
#define Wn   32
#define NH   8
#define HD   8
#define BS   (Bn*Sn)        // 512
#define TILES (BS*Cn)       // 32768
#define O3   (3*Cn)         // 192
#define En   64

// Scratch (device globals; no allocation)
__device__ float g_X[TILES*8];          // input rfft2 modes: [00r,00i(0),10r,10i,01r,01i,11r,11i]
__device__ float g_Qf[Bn*NH*Sn*56];     // Q features (pre-scaled)
__device__ float g_Kf[Bn*NH*Sn*56];
__device__ float g_Vf[Bn*NH*Sn*56];
__device__ float g_bias[NH*Sn*Sn];
__device__ float g_O[Bn*NH*Sn*56];      // attention output features
__device__ float g_G[TILES*8];          // final output modes per (b,s,c)

// ---------------------------------------------------------------------------
// K1: extract the 4 low rfft2 modes of each 32x32 tile of seq.
// One warp per tile; lane = w column; loop over h rows (coalesced 128B/row).
// F00 = sum x ; F10 = sum x e^{-i th} ; F01 = sum x e^{-i pw} ; F11 = sum x e^{-i(th+pw)}
// ---------------------------------------------------------------------------
__global__ void k_modes(const float* __restrict__ x) {
    __shared__ float tc[32], ts[32];
    if (threadIdx.x < 32) {
        float s, c;
        sincospif((float)threadIdx.x * (1.0f/16.0f), &s, &c);  // 2*pi*h/32
        tc[threadIdx.x] = c; ts[threadIdx.x] = s;
    }
    __syncthreads();
    int tile = blockIdx.x * 8 + (threadIdx.x >> 5);
    int lane = threadIdx.x & 31;
    const float* p = x + (size_t)tile * 1024 + lane;

    float a = 0.f, bc = 0.f, bs = 0.f;
#pragma unroll
    for (int h = 0; h < 32; h++) {
        float v = p[h * 32];
        a += v;
        bc = fmaf(v, tc[h], bc);
        bs = fmaf(v, ts[h], bs);
    }
    float cw = tc[lane], sw = ts[lane];
    float r[7];
    r[0] = a;                       // F00 (real)
    r[1] = bc;  r[2] = bs;          // sum x cos(th), sum x sin(th)
    r[3] = a * cw; r[4] = a * sw;   // sum x cos(pw), sum x sin(pw)
    r[5] = bc * cw - bs * sw;       // sum x cos(th+pw)
    r[6] = bs * cw + bc * sw;       // sum x sin(th+pw)
#pragma unroll
    for (int k = 0; k < 7; k++) {
#pragma unroll
        for (int off = 16; off; off >>= 1)
            r[k] += __shfl_xor_sync(0xffffffffu, r[k], off);
    }
    if (lane == 0) {
        float* dst = g_X + (size_t)tile * 8;
        dst[0] = r[0]; dst[1] = 0.f;
        dst[2] = r[1]; dst[3] = -r[2];   // F10 = c - i s
        dst[4] = r[3]; dst[5] = -r[4];   // F01
        dst[6] = r[5]; dst[7] = -r[6];   // F11
    }
}

// ---------------------------------------------------------------------------
// K2: QKV spectral mixing. Y[bs,o,mode] = sum_c X[bs,c,mode] * Wqkv[c,o,mode].
// Then convert to 7-feature vectors; Q gets the Gram weights * global scale.
// grid (128,4): 4 bs-rows per block, 48 o per block; blockDim 192 (o_l x r).
// ---------------------------------------------------------------------------
__global__ void k_qkv_mix(const float* __restrict__ wr, const float* __restrict__ wi) {
    __shared__ float Xs[4 * 64 * 8];  // 8KB
    const int bs0 = blockIdx.x * 4;
    const int o0  = blockIdx.y * 48;
    const int t = threadIdx.x;
    for (int idx = t; idx < 4 * 64 * 8; idx += 192)
        Xs[idx] = g_X[(size_t)bs0 * 512 + idx];
    __syncthreads();

    const int o_l = t % 48, r = t / 48;
    const int o = o0 + o_l;
    const int bs = bs0 + r;

    float a0 = 0.f, a1 = 0.f, a2 = 0.f, a3 = 0.f, a4 = 0.f, a5 = 0.f, a6 = 0.f;
    const float4* wr4 = (const float4*)wr;
    const float4* wi4 = (const float4*)wi;
#pragma unroll 4
    for (int c = 0; c < 64; c++) {
        float4 x0 = *(const float4*)&Xs[(r * 64 + c) * 8];
        float4 x1 = *(const float4*)&Xs[(r * 64 + c) * 8 + 4];
        float4 w0 = wr4[c * O3 + o];   // [kx,ky] = (0,0),(0,1),(1,0),(1,1)
        float4 w1 = wi4[c * O3 + o];
        // mode00 (X real -> only Re needed)
        a0 = fmaf(x0.x, w0.x, a0);
        // mode10: F10=(x0.z,x0.w), w=(w0.z,w1.z)
        a1 = fmaf(x0.z, w0.z, fmaf(-x0.w, w1.z, a1));
        a2 = fmaf(x0.z, w1.z, fmaf( x0.w, w0.z, a2));
        // mode01: F01=(x1.x,x1.y), w=(w0.y,w1.y)
        a3 = fmaf(x1.x, w0.y, fmaf(-x1.y, w1.y, a3));
        a4 = fmaf(x1.x, w1.y, fmaf( x1.y, w0.y, a4));
        // mode11: F11=(x1.z,x1.w), w=(w0.w,w1.w)
        a5 = fmaf(x1.z, w0.w, fmaf(-x1.w, w1.w, a5));
        a6 = fmaf(x1.z, w1.w, fmaf( x1.w, w0.w, a6));
    }
    const int which = o >> 6, rem = o & 63;
    const int h = rem >> 3, d = rem & 7;
    const int b = bs >> 6, s = bs & 63;
    size_t base = (((size_t)(b * NH + h) * Sn) + s) * 56 + d * 7;
    if (which == 0) {
        // score scale: (1/(H*W*sqrt(hd))) * (1/(H*W)), Gram weights [1,.5,.5,2,2,2,2]
        const float cs = 1.0f / (1048576.0f * 2.82842712474619f);
        g_Qf[base + 0] = a0 * cs;
        g_Qf[base + 1] = a1 * (0.5f * cs);
        g_Qf[base + 2] = a2 * (0.5f * cs);
        g_Qf[base + 3] = a3 * (2.0f * cs);
        g_Qf[base + 4] = a4 * (2.0f * cs);
        g_Qf[base + 5] = a5 * (2.0f * cs);
        g_Qf[base + 6] = a6 * (2.0f * cs);
    } else {
        float* dst = (which == 1) ? g_Kf : g_Vf;
        dst[base + 0] = a0; dst[base + 1] = a1; dst[base + 2] = a2;
        dst[base + 3] = a3; dst[base + 4] = a4; dst[base + 5] = a5; dst[base + 6] = a6;
    }
}

// ---------------------------------------------------------------------------
// K3: Swin-v2 log-CPB bias. One thread per (i,j) pair.
// ---------------------------------------------------------------------------
__device__ __forceinline__ float signlog2(float x) {
    return copysignf(log2f(1.0f + fabsf(x)), x);
}
__global__ void k_bias(const float* __restrict__ w1, const float* __restrict__ b1,
                       const float* __restrict__ w2, const int* __restrict__ nsy_p) {
    int idx = blockIdx.x * blockDim.x + threadIdx.x;
    if (idx >= Sn * Sn) return;
    int i = idx >> 6, j = idx & 63;
    int ny = *nsy_p;
    float r0 = signlog2((float)(i / ny - j / ny));
    float r1 = signlog2((float)(i % ny - j % ny));
    float out[NH];
#pragma unroll
    for (int hh = 0; hh < NH; hh++) out[hh] = 0.f;
    for (int e = 0; e < En; e++) {
        float hv = fmaxf(fmaf(r0, w1[e], fmaf(r1, w1[En + e], b1[e])), 0.f);
#pragma unroll
        for (int hh = 0; hh < NH; hh++) out[hh] = fmaf(hv, w2[e * NH + hh], out[hh]);
    }
#pragma unroll
    for (int hh = 0; hh < NH; hh++) g_bias[hh * (Sn * Sn) + idx] = out[hh];
}

// ---------------------------------------------------------------------------
// K4: attention in 56-dim feature space. One block per (b,h), 256 threads.
// ---------------------------------------------------------------------------
__global__ void k_attn() {
    const int bh = blockIdx.x;
    const int h = bh & (NH - 1);
    __shared__ float Ks[64 * 60];     // row stride 60 (16B aligned, low conflicts)
    __shared__ float Vs[64 * 60];
    __shared__ float Sc[64 * 65];
    const int t = threadIdx.x;

    const float* kg = g_Kf + (size_t)bh * 64 * 56;
    const float* vg = g_Vf + (size_t)bh * 64 * 56;
    for (int idx = t; idx < 64 * 56; idx += 256) {
        int row = idx / 56, m = idx % 56;
        Ks[row * 60 + m] = kg[idx];
        Vs[row * 60 + m] = vg[idx];
    }
    __syncthreads();

    const int i = t >> 2, part = t & 3;
    float q[56];
    const float* qg = g_Qf + ((size_t)bh * 64 + i) * 56;
#pragma unroll
    for (int m = 0; m < 56; m++) q[m] = __ldg(&qg[m]);

#pragma unroll
    for (int jj = 0; jj < 16; jj++) {
        int j = part * 16 + jj;
        float acc = g_bias[h * (Sn * Sn) + i * 64 + j];
        const float* kr = &Ks[j * 60];
#pragma unroll
        for (int m = 0; m < 56; m += 4) {
            float4 kv = *(const float4*)&kr[m];
            acc = fmaf(q[m], kv.x, acc);
            acc = fmaf(q[m + 1], kv.y, acc);
            acc = fmaf(q[m + 2], kv.z, acc);
            acc = fmaf(q[m + 3], kv.w, acc);
        }
        Sc[i * 65 + j] = acc;
    }
    __syncthreads();

    if (t < 64) {
        float mx = -1e30f;
#pragma unroll
        for (int j = 0; j < 64; j++) mx = fmaxf(mx, Sc[t * 65 + j]);
        float sum = 0.f;
#pragma unroll
        for (int j = 0; j < 64; j++) {
            float e = expf(Sc[t * 65 + j] - mx);
            Sc[t * 65 + j] = e;
            sum += e;
        }
        float inv = 1.0f / sum;
#pragma unroll
        for (int j = 0; j < 64; j++) Sc[t * 65 + j] *= inv;
    }
    __syncthreads();

    float acc[14];
#pragma unroll
    for (int mm = 0; mm < 14; mm++) acc[mm] = 0.f;
    const int m0 = part * 14;
#pragma unroll 4
    for (int j = 0; j < 64; j++) {
        float a = Sc[i * 65 + j];
        const float* vr = &Vs[j * 60 + m0];
#pragma unroll
        for (int mm = 0; mm < 14; mm++) acc[mm] = fmaf(a, vr[mm], acc[mm]);
    }
    float* og = g_O + ((size_t)bh * 64 + i) * 56 + m0;
#pragma unroll
    for (int mm = 0; mm < 14; mm++) og[mm] = acc[mm];
}

// ---------------------------------------------------------------------------
// K5: output spectral mixing. Forward modes of attention output:
// F00=A, F10=(Br+iBi)/2, F01=Cr+iCi, F11=Dr+iDi. Then G[o]=sum_c F[c]*Wout[c,o].
// grid (128,2): 4 bs-rows x 32 o per block; blockDim 128.
// ---------------------------------------------------------------------------
__global__ void k_out_mix(const float* __restrict__ wr, const float* __restrict__ wi) {
    __shared__ float Fs[4 * 64 * 8];  // 8KB
    const int bs0 = blockIdx.x * 4;
    const int o0  = blockIdx.y * 32;
    const int t = threadIdx.x;

    for (int idx = t; idx < 4 * 64; idx += 128) Fs[idx * 8 + 1] = 0.f;
    for (int idx = t; idx < 4 * 64 * 7; idx += 128) {
        int r = idx / 448, rem = idx % 448;
        int c = rem / 7, m = rem % 7;
        int bsv = bs0 + r;
        int b = bsv >> 6, s = bsv & 63;
        float v = g_O[(((size_t)(b * NH + (c >> 3)) * Sn) + s) * 56 + (c & 7) * 7 + m];
        int slot = (m == 0) ? 0 : (m + 1);
        float sc = (m == 1 || m == 2) ? 0.5f : 1.0f;   // F10 = B/2
        Fs[(r * 64 + c) * 8 + slot] = v * sc;
    }
    __syncthreads();

    const int o_l = t & 31, r = t >> 5;
    const int o = o0 + o_l;
    const int bs = bs0 + r;

    float a0 = 0.f, a1 = 0.f, a2 = 0.f, a3 = 0.f, a4 = 0.f, a5 = 0.f, a6 = 0.f;
    const float4* wr4 = (const float4*)wr;
    const float4* wi4 = (const float4*)wi;
#pragma unroll 4
    for (int c = 0; c < 64; c++) {
        float4 x0 = *(const float4*)&Fs[(r * 64 + c) * 8];
        float4 x1 = *(const float4*)&Fs[(r * 64 + c) * 8 + 4];
        float4 w0 = wr4[c * Cn + o];
        float4 w1 = wi4[c * Cn + o];
        a0 = fmaf(x0.x, w0.x, a0);                                  // Re G00
        a1 = fmaf(x0.z, w0.z, fmaf(-x0.w, w1.z, a1));               // G10
        a2 = fmaf(x0.z, w1.z, fmaf( x0.w, w0.z, a2));
        a3 = fmaf(x1.x, w0.y, fmaf(-x1.y, w1.y, a3));               // G01
        a4 = fmaf(x1.x, w1.y, fmaf( x1.y, w0.y, a4));
        a5 = fmaf(x1.z, w0.w, fmaf(-x1.w, w1.w, a5));               // G11
        a6 = fmaf(x1.z, w1.w, fmaf( x1.w, w0.w, a6));
    }
    float* dst = g_G + ((size_t)bs * 64 + o) * 8;
    dst[0] = a0; dst[1] = 0.f;
    dst[2] = a1; dst[3] = a2;
    dst[4] = a3; dst[5] = a4;
    dst[6] = a5; dst[7] = a6;
}

// ---------------------------------------------------------------------------
// K6: synthesis. f(h,w) = (1/HW)[ReG00 + Re(G10 e^{i th}) + 2Re(G01 e^{i pw})
//                                 + 2Re(G11 e^{i(th+pw)})]
// One warp per tile; lane = w.
// ---------------------------------------------------------------------------
__global__ void k_synth(float* __restrict__ out) {
    __shared__ float tc[32], ts[32];
    if (threadIdx.x < 32) {
        float s, c;
        sincospif((float)threadIdx.x * (1.0f/16.0f), &s, &c);
        tc[threadIdx.x] = c; ts[threadIdx.x] = s;
    }
    __syncthreads();
    int tile = blockIdx.x * 8 + (threadIdx.x >> 5);
    int lane = threadIdx.x & 31;
    const float* g = g_G + (size_t)tile * 8;
    float4 g0 = *(const float4*)g;        // G00r, -, G10r, G10i
    float4 g1 = *(const float4*)(g + 4);  // G01r, G01i, G11r, G11i
    float cw = tc[lane], sw = ts[lane];
    const float inv = 1.0f / 1024.0f;
    float P0 = (g0.x + 2.0f * (g1.x * cw - g1.y * sw)) * inv;
    float Pc = (g0.z + 2.0f * (g1.z * cw - g1.w * sw)) * inv;
    float Ps = (-g0.w - 2.0f * (g1.z * sw + g1.w * cw)) * inv;
    float* dst = out + (size_t)tile * 1024 + lane;
#pragma unroll
    for (int h = 0; h < 32; h++)
        dst[h * 32] = fmaf(Pc, tc[h], fmaf(Ps, ts[h], P0));
}

// ---------------------------------------------------------------------------
extern "C" void kernel_launch(void* const* d_in, const int* in_sizes, int n_in,
                              void* d_out, int out_size) {
    const float* seq = (const float*)d_in[0];
    const float* wqr = (const float*)d_in[1];
    const float* wqi = (const float*)d_in[2];
    const float* wor = (const float*)d_in[3];
    const float* woi = (const float*)d_in[4];
    const float* w1  = (const float*)d_in[5];
    const float* b1  = (const float*)d_in[6];
    const float* w2  = (const float*)d_in[7];
    const int* nsy   = (const int*)d_in[9];
    float* out = (float*)d_out;

    k_modes<<<TILES / 8, 256>>>(seq);
    k_bias<<<16, 256>>>(w1, b1, w2, nsy);
    k_qkv_mix<<<dim3(128, 4), 192>>>(wqr, wqi);
    k_attn<<<Bn * NH, 256>>>();
    k_out_mix<<<dim3(128, 2), 128>>>(wor, woi);
    k_synth<<<TILES / 8, 256>>>(out);
}

// round 2
// speedup vs baseline: 1.2156x; 1.2156x over previous
#include <cuda_runtime.h>
#include <math.h>

#define Bn   8
#define Sn   64
#define Cn   64
#define Hn   32
#define Wn   32
#define NH   8
#define HD   8
#define BS   (Bn*Sn)        // 512
#define TILES (BS*Cn)       // 32768
#define O3   (3*Cn)         // 192
#define En   64

__device__ float g_X[TILES*8];
__device__ float g_Qf[Bn*NH*Sn*56];
__device__ float g_Kf[Bn*NH*Sn*56];
__device__ float g_Vf[Bn*NH*Sn*56];
__device__ float g_bias[NH*Sn*Sn];
__device__ float g_O[Bn*NH*Sn*56];
__device__ float g_G[TILES*8];

// ---------------------------------------------------------------------------
// K1: extract 4 low rfft2 modes per 32x32 tile. One warp per tile.
// ---------------------------------------------------------------------------
__global__ void k_modes(const float* __restrict__ x) {
    __shared__ float tc[32], ts[32];
    if (threadIdx.x < 32) {
        float s, c;
        sincospif((float)threadIdx.x * (1.0f/16.0f), &s, &c);
        tc[threadIdx.x] = c; ts[threadIdx.x] = s;
    }
    __syncthreads();
    int tile = blockIdx.x * 8 + (threadIdx.x >> 5);
    int lane = threadIdx.x & 31;
    const float* p = x + (size_t)tile * 1024 + lane;

    float a = 0.f, bc = 0.f, bs = 0.f;
#pragma unroll
    for (int h = 0; h < 32; h++) {
        float v = p[h * 32];
        a += v;
        bc = fmaf(v, tc[h], bc);
        bs = fmaf(v, ts[h], bs);
    }
    float cw = tc[lane], sw = ts[lane];
    float r[7];
    r[0] = a;
    r[1] = bc;  r[2] = bs;
    r[3] = a * cw; r[4] = a * sw;
    r[5] = bc * cw - bs * sw;
    r[6] = bs * cw + bc * sw;
#pragma unroll
    for (int k = 0; k < 7; k++) {
#pragma unroll
        for (int off = 16; off; off >>= 1)
            r[k] += __shfl_xor_sync(0xffffffffu, r[k], off);
    }
    if (lane == 0) {
        float* dst = g_X + (size_t)tile * 8;
        dst[0] = r[0]; dst[1] = 0.f;
        dst[2] = r[1]; dst[3] = -r[2];
        dst[4] = r[3]; dst[5] = -r[4];
        dst[6] = r[5]; dst[7] = -r[6];
    }
}

// ---------------------------------------------------------------------------
// K2: QKV spectral mixing. Block = 16 bs x 32 o; 256 thr = 8 grp x 32 o_l,
// each grp owns 2 bs rows. Warp lanes differ only in o -> X smem reads are
// uniform broadcasts; weight LDGs coalesced + L1-resident.
// ---------------------------------------------------------------------------
__global__ void k_qkv_mix(const float* __restrict__ wr, const float* __restrict__ wi) {
    __shared__ float Xs[16 * 64 * 8];  // 32KB
    const int bs0 = blockIdx.x * 16;
    const int o0  = blockIdx.y * 32;
    const int t = threadIdx.x;
    {
        const float4* gx = (const float4*)(g_X + (size_t)bs0 * 512);
        float4* xs4 = (float4*)Xs;
#pragma unroll
        for (int idx = t; idx < 16 * 64 * 2; idx += 256)
            xs4[idx] = gx[idx];
    }
    __syncthreads();

    const int o_l = t & 31, grp = t >> 5;
    const int o = o0 + o_l;
    const int row0 = grp * 2;

    float acc[2][7];
#pragma unroll
    for (int rr = 0; rr < 2; rr++)
#pragma unroll
        for (int m = 0; m < 7; m++) acc[rr][m] = 0.f;

    const float4* wr4 = (const float4*)wr;
    const float4* wi4 = (const float4*)wi;
#pragma unroll 4
    for (int c = 0; c < 64; c++) {
        float4 w0 = wr4[c * O3 + o];
        float4 w1 = wi4[c * O3 + o];
#pragma unroll
        for (int rr = 0; rr < 2; rr++) {
            float4 x0 = *(const float4*)&Xs[((row0 + rr) * 64 + c) * 8];
            float4 x1 = *(const float4*)&Xs[((row0 + rr) * 64 + c) * 8 + 4];
            acc[rr][0] = fmaf(x0.x, w0.x, acc[rr][0]);
            acc[rr][1] = fmaf(x0.z, w0.z, fmaf(-x0.w, w1.z, acc[rr][1]));
            acc[rr][2] = fmaf(x0.z, w1.z, fmaf( x0.w, w0.z, acc[rr][2]));
            acc[rr][3] = fmaf(x1.x, w0.y, fmaf(-x1.y, w1.y, acc[rr][3]));
            acc[rr][4] = fmaf(x1.x, w1.y, fmaf( x1.y, w0.y, acc[rr][4]));
            acc[rr][5] = fmaf(x1.z, w0.w, fmaf(-x1.w, w1.w, acc[rr][5]));
            acc[rr][6] = fmaf(x1.z, w1.w, fmaf( x1.w, w0.w, acc[rr][6]));
        }
    }
    const int which = o >> 6, rem = o & 63;
    const int h = rem >> 3, d = rem & 7;
#pragma unroll
    for (int rr = 0; rr < 2; rr++) {
        const int bs = bs0 + row0 + rr;
        const int b = bs >> 6, s = bs & 63;
        size_t base = (((size_t)(b * NH + h) * Sn) + s) * 56 + d * 7;
        if (which == 0) {
            const float cs = 1.0f / (1048576.0f * 2.82842712474619f);
            g_Qf[base + 0] = acc[rr][0] * cs;
            g_Qf[base + 1] = acc[rr][1] * (0.5f * cs);
            g_Qf[base + 2] = acc[rr][2] * (0.5f * cs);
            g_Qf[base + 3] = acc[rr][3] * (2.0f * cs);
            g_Qf[base + 4] = acc[rr][4] * (2.0f * cs);
            g_Qf[base + 5] = acc[rr][5] * (2.0f * cs);
            g_Qf[base + 6] = acc[rr][6] * (2.0f * cs);
        } else {
            float* dst = (which == 1) ? g_Kf : g_Vf;
#pragma unroll
            for (int m = 0; m < 7; m++) dst[base + m] = acc[rr][m];
        }
    }
}

// ---------------------------------------------------------------------------
// K3: log-CPB bias.
// ---------------------------------------------------------------------------
__device__ __forceinline__ float signlog2(float x) {
    return copysignf(log2f(1.0f + fabsf(x)), x);
}
__global__ void k_bias(const float* __restrict__ w1, const float* __restrict__ b1,
                       const float* __restrict__ w2, const int* __restrict__ nsy_p) {
    int idx = blockIdx.x * blockDim.x + threadIdx.x;
    if (idx >= Sn * Sn) return;
    int i = idx >> 6, j = idx & 63;
    int ny = *nsy_p;
    float r0 = signlog2((float)(i / ny - j / ny));
    float r1 = signlog2((float)(i % ny - j % ny));
    float out[NH];
#pragma unroll
    for (int hh = 0; hh < NH; hh++) out[hh] = 0.f;
    for (int e = 0; e < En; e++) {
        float hv = fmaxf(fmaf(r0, w1[e], fmaf(r1, w1[En + e], b1[e])), 0.f);
#pragma unroll
        for (int hh = 0; hh < NH; hh++) out[hh] = fmaf(hv, w2[e * NH + hh], out[hh]);
    }
#pragma unroll
    for (int hh = 0; hh < NH; hh++) g_bias[hh * (Sn * Sn) + idx] = out[hh];
}

// ---------------------------------------------------------------------------
// K4: attention, 56-dim feature space. grid (64 bh, 4 i-chunks), 256 thr.
// thread = (i_l 0..15, part 0..15); part owns 4 j's (j = jj*16+part) in the
// score phase, then an m-chunk of 4 in the AV phase. Softmax fully parallel
// via 16-lane shuffles + __expf.
// ---------------------------------------------------------------------------
__global__ void k_attn() {
    const int bh = blockIdx.x;
    const int h = bh & (NH - 1);
    const int i0 = blockIdx.y * 16;
    __shared__ float Ks[64 * 60];
    __shared__ float Vs[64 * 60];
    __shared__ float Sc[16 * 65];
    const int t = threadIdx.x;

    const float* kg = g_Kf + (size_t)bh * 64 * 56;
    const float* vg = g_Vf + (size_t)bh * 64 * 56;
    for (int idx = t; idx < 64 * 56; idx += 256) {
        int row = idx / 56, m = idx % 56;
        Ks[row * 60 + m] = kg[idx];
        Vs[row * 60 + m] = vg[idx];
    }

    const int i_l = t >> 4, part = t & 15;
    const int i = i0 + i_l;
    float q[56];
    const float* qg = g_Qf + ((size_t)bh * 64 + i) * 56;
#pragma unroll
    for (int m = 0; m < 56; m++) q[m] = __ldg(&qg[m]);
    __syncthreads();

    float sc[4];
#pragma unroll
    for (int jj = 0; jj < 4; jj++) {
        int j = jj * 16 + part;
        float a = g_bias[h * (Sn * Sn) + i * 64 + j];
        const float* kr = &Ks[j * 60];
#pragma unroll
        for (int m = 0; m < 56; m += 4) {
            float4 kv = *(const float4*)&kr[m];
            a = fmaf(q[m],     kv.x, a);
            a = fmaf(q[m + 1], kv.y, a);
            a = fmaf(q[m + 2], kv.z, a);
            a = fmaf(q[m + 3], kv.w, a);
        }
        sc[jj] = a;
    }
    // row softmax across the 16-lane group
    float mx = fmaxf(fmaxf(sc[0], sc[1]), fmaxf(sc[2], sc[3]));
#pragma unroll
    for (int off = 8; off; off >>= 1)
        mx = fmaxf(mx, __shfl_xor_sync(0xffffffffu, mx, off, 16));
    float e0 = __expf(sc[0] - mx), e1 = __expf(sc[1] - mx);
    float e2 = __expf(sc[2] - mx), e3 = __expf(sc[3] - mx);
    float sum = (e0 + e1) + (e2 + e3);
#pragma unroll
    for (int off = 8; off; off >>= 1)
        sum += __shfl_xor_sync(0xffffffffu, sum, off, 16);
    float inv = 1.0f / sum;
    Sc[i_l * 65 +  0 + part] = e0 * inv;
    Sc[i_l * 65 + 16 + part] = e1 * inv;
    Sc[i_l * 65 + 32 + part] = e2 * inv;
    Sc[i_l * 65 + 48 + part] = e3 * inv;
    __syncthreads();

    if (part < 14) {
        const int m0 = part * 4;
        float a0 = 0.f, a1 = 0.f, a2 = 0.f, a3 = 0.f;
        const float* sr = &Sc[i_l * 65];
#pragma unroll 8
        for (int j = 0; j < 64; j++) {
            float a = sr[j];
            float4 vv = *(const float4*)&Vs[j * 60 + m0];
            a0 = fmaf(a, vv.x, a0);
            a1 = fmaf(a, vv.y, a1);
            a2 = fmaf(a, vv.z, a2);
            a3 = fmaf(a, vv.w, a3);
        }
        float* og = g_O + ((size_t)bh * 64 + i) * 56 + m0;
        og[0] = a0; og[1] = a1; og[2] = a2; og[3] = a3;
    }
}

// ---------------------------------------------------------------------------
// K5: output spectral mixing. grid (64 bs-groups of 8, 2 o-groups of 32);
// 256 thr = 8 grp (1 bs row each) x 32 o_l. Broadcast smem X.
// ---------------------------------------------------------------------------
__global__ void k_out_mix(const float* __restrict__ wr, const float* __restrict__ wi) {
    __shared__ float Fs[8 * 64 * 8];  // 16KB
    const int bs0 = blockIdx.x * 8;
    const int o0  = blockIdx.y * 32;
    const int t = threadIdx.x;

    for (int idx = t; idx < 8 * 64; idx += 256) Fs[idx * 8 + 1] = 0.f;
    for (int idx = t; idx < 8 * 64 * 7; idx += 256) {
        int r = idx / 448, rem = idx % 448;
        int c = rem / 7, m = rem % 7;
        int bsv = bs0 + r;
        int b = bsv >> 6, s = bsv & 63;
        float v = g_O[(((size_t)(b * NH + (c >> 3)) * Sn) + s) * 56 + (c & 7) * 7 + m];
        int slot = (m == 0) ? 0 : (m + 1);
        float sc = (m == 1 || m == 2) ? 0.5f : 1.0f;
        Fs[(r * 64 + c) * 8 + slot] = v * sc;
    }
    __syncthreads();

    const int o_l = t & 31, grp = t >> 5;
    const int o = o0 + o_l;

    float a0 = 0.f, a1 = 0.f, a2 = 0.f, a3 = 0.f, a4 = 0.f, a5 = 0.f, a6 = 0.f;
    const float4* wr4 = (const float4*)wr;
    const float4* wi4 = (const float4*)wi;
#pragma unroll 4
    for (int c = 0; c < 64; c++) {
        float4 x0 = *(const float4*)&Fs[(grp * 64 + c) * 8];
        float4 x1 = *(const float4*)&Fs[(grp * 64 + c) * 8 + 4];
        float4 w0 = wr4[c * Cn + o];
        float4 w1 = wi4[c * Cn + o];
        a0 = fmaf(x0.x, w0.x, a0);
        a1 = fmaf(x0.z, w0.z, fmaf(-x0.w, w1.z, a1));
        a2 = fmaf(x0.z, w1.z, fmaf( x0.w, w0.z, a2));
        a3 = fmaf(x1.x, w0.y, fmaf(-x1.y, w1.y, a3));
        a4 = fmaf(x1.x, w1.y, fmaf( x1.y, w0.y, a4));
        a5 = fmaf(x1.z, w0.w, fmaf(-x1.w, w1.w, a5));
        a6 = fmaf(x1.z, w1.w, fmaf( x1.w, w0.w, a6));
    }
    float* dst = g_G + (((size_t)(bs0 + grp)) * 64 + o) * 8;
    dst[0] = a0; dst[1] = 0.f;
    dst[2] = a1; dst[3] = a2;
    dst[4] = a3; dst[5] = a4;
    dst[6] = a5; dst[7] = a6;
}

// ---------------------------------------------------------------------------
// K6: synthesis. One warp per tile.
// ---------------------------------------------------------------------------
__global__ void k_synth(float* __restrict__ out) {
    __shared__ float tc[32], ts[32];
    if (threadIdx.x < 32) {
        float s, c;
        sincospif((float)threadIdx.x * (1.0f/16.0f), &s, &c);
        tc[threadIdx.x] = c; ts[threadIdx.x] = s;
    }
    __syncthreads();
    int tile = blockIdx.x * 8 + (threadIdx.x >> 5);
    int lane = threadIdx.x & 31;
    const float* g = g_G + (size_t)tile * 8;
    float4 g0 = *(const float4*)g;
    float4 g1 = *(const float4*)(g + 4);
    float cw = tc[lane], sw = ts[lane];
    const float inv = 1.0f / 1024.0f;
    float P0 = (g0.x + 2.0f * (g1.x * cw - g1.y * sw)) * inv;
    float Pc = (g0.z + 2.0f * (g1.z * cw - g1.w * sw)) * inv;
    float Ps = (-g0.w - 2.0f * (g1.z * sw + g1.w * cw)) * inv;
    float* dst = out + (size_t)tile * 1024 + lane;
#pragma unroll
    for (int h = 0; h < 32; h++)
        dst[h * 32] = fmaf(Pc, tc[h], fmaf(Ps, ts[h], P0));
}

// ---------------------------------------------------------------------------
extern "C" void kernel_launch(void* const* d_in, const int* in_sizes, int n_in,
                              void* d_out, int out_size) {
    const float* seq = (const float*)d_in[0];
    const float* wqr = (const float*)d_in[1];
    const float* wqi = (const float*)d_in[2];
    const float* wor = (const float*)d_in[3];
    const float* woi = (const float*)d_in[4];
    const float* w1  = (const float*)d_in[5];
    const float* b1  = (const float*)d_in[6];
    const float* w2  = (const float*)d_in[7];
    const int* nsy   = (const int*)d_in[9];
    float* out = (float*)d_out;

    k_modes<<<TILES / 8, 256>>>(seq);
    k_bias<<<16, 256>>>(w1, b1, w2, nsy);
    k_qkv_mix<<<dim3(32, 6), 256>>>(wqr, wqi);
    k_attn<<<dim3(Bn * NH, 4), 256>>>();
    k_out_mix<<<dim3(64, 2), 256>>>(wor, woi);
    k_synth<<<TILES / 8, 256>>>(out);
}

// round 3
// speedup vs baseline: 1.4197x; 1.1679x over previous
#include <cuda_runtime.h>
#include <math.h>

#define Bn   8
#define Sn   64
#define Cn   64
#define Hn   32
#define Wn   32
#define NH   8
#define HD   8
#define BS   (Bn*Sn)        // 512
#define TILES (BS*Cn)       // 32768
#define O3   (3*Cn)         // 192
#define En   64

__device__ float g_X[TILES*8];
__device__ float g_Qf[Bn*NH*Sn*56];
__device__ float g_Kf[Bn*NH*Sn*56];
__device__ float g_Vf[Bn*NH*Sn*56];
__device__ float g_bias[NH*Sn*Sn];
__device__ float g_O[Bn*NH*Sn*56];

// ---------------------------------------------------------------------------
// K1: extract 4 low rfft2 modes per 32x32 tile. One warp per tile.
// float4 loads: thread = 4 w-columns x (h0 + 4*it) rows -> 8 LDG.128/warp-tile.
// ---------------------------------------------------------------------------
__global__ void k_modes(const float* __restrict__ x) {
    __shared__ float tc[32], ts[32];
    if (threadIdx.x < 32) {
        float s, c;
        sincospif((float)threadIdx.x * (1.0f/16.0f), &s, &c);
        tc[threadIdx.x] = c; ts[threadIdx.x] = s;
    }
    __syncthreads();
    int tile = blockIdx.x * 8 + (threadIdx.x >> 5);
    int lane = threadIdx.x & 31;
    const float4* p = (const float4*)(x + (size_t)tile * 1024) + lane;
    const int w0 = (lane & 7) * 4;
    const int h0 = lane >> 3;

    float a[4]  = {0.f, 0.f, 0.f, 0.f};
    float bc[4] = {0.f, 0.f, 0.f, 0.f};
    float bs[4] = {0.f, 0.f, 0.f, 0.f};
#pragma unroll
    for (int it = 0; it < 8; it++) {
        float4 v = p[it * 32];
        int hh = h0 + it * 4;
        float c = tc[hh], s = ts[hh];
        a[0] += v.x; bc[0] = fmaf(v.x, c, bc[0]); bs[0] = fmaf(v.x, s, bs[0]);
        a[1] += v.y; bc[1] = fmaf(v.y, c, bc[1]); bs[1] = fmaf(v.y, s, bs[1]);
        a[2] += v.z; bc[2] = fmaf(v.z, c, bc[2]); bs[2] = fmaf(v.z, s, bs[2]);
        a[3] += v.w; bc[3] = fmaf(v.w, c, bc[3]); bs[3] = fmaf(v.w, s, bs[3]);
    }
    float r[7] = {0.f, 0.f, 0.f, 0.f, 0.f, 0.f, 0.f};
#pragma unroll
    for (int j = 0; j < 4; j++) {
        float cw = tc[w0 + j], sw = ts[w0 + j];
        r[0] += a[j];
        r[1] += bc[j];
        r[2] += bs[j];
        r[3] = fmaf(a[j], cw, r[3]);
        r[4] = fmaf(a[j], sw, r[4]);
        r[5] += bc[j] * cw - bs[j] * sw;
        r[6] += bs[j] * cw + bc[j] * sw;
    }
#pragma unroll
    for (int k = 0; k < 7; k++) {
#pragma unroll
        for (int off = 16; off; off >>= 1)
            r[k] += __shfl_xor_sync(0xffffffffu, r[k], off);
    }
    if (lane == 0) {
        float* dst = g_X + (size_t)tile * 8;
        dst[0] = r[0]; dst[1] = 0.f;
        dst[2] = r[1]; dst[3] = -r[2];
        dst[4] = r[3]; dst[5] = -r[4];
        dst[6] = r[5]; dst[7] = -r[6];
    }
}

// ---------------------------------------------------------------------------
// K2: QKV spectral mixing. Block = 16 bs x 32 o; 256 thr = 8 grp x 32 o_l,
// each grp owns 2 bs rows. X smem reads are uniform broadcasts.
// ---------------------------------------------------------------------------
__global__ void k_qkv_mix(const float* __restrict__ wr, const float* __restrict__ wi) {
    __shared__ float Xs[16 * 64 * 8];  // 32KB
    const int bs0 = blockIdx.x * 16;
    const int o0  = blockIdx.y * 32;
    const int t = threadIdx.x;
    {
        const float4* gx = (const float4*)(g_X + (size_t)bs0 * 512);
        float4* xs4 = (float4*)Xs;
#pragma unroll
        for (int idx = t; idx < 16 * 64 * 2; idx += 256)
            xs4[idx] = gx[idx];
    }
    __syncthreads();

    const int o_l = t & 31, grp = t >> 5;
    const int o = o0 + o_l;
    const int row0 = grp * 2;

    float acc[2][7];
#pragma unroll
    for (int rr = 0; rr < 2; rr++)
#pragma unroll
        for (int m = 0; m < 7; m++) acc[rr][m] = 0.f;

    const float4* wr4 = (const float4*)wr;
    const float4* wi4 = (const float4*)wi;
#pragma unroll 4
    for (int c = 0; c < 64; c++) {
        float4 w0 = wr4[c * O3 + o];
        float4 w1 = wi4[c * O3 + o];
#pragma unroll
        for (int rr = 0; rr < 2; rr++) {
            float4 x0 = *(const float4*)&Xs[((row0 + rr) * 64 + c) * 8];
            float4 x1 = *(const float4*)&Xs[((row0 + rr) * 64 + c) * 8 + 4];
            acc[rr][0] = fmaf(x0.x, w0.x, acc[rr][0]);
            acc[rr][1] = fmaf(x0.z, w0.z, fmaf(-x0.w, w1.z, acc[rr][1]));
            acc[rr][2] = fmaf(x0.z, w1.z, fmaf( x0.w, w0.z, acc[rr][2]));
            acc[rr][3] = fmaf(x1.x, w0.y, fmaf(-x1.y, w1.y, acc[rr][3]));
            acc[rr][4] = fmaf(x1.x, w1.y, fmaf( x1.y, w0.y, acc[rr][4]));
            acc[rr][5] = fmaf(x1.z, w0.w, fmaf(-x1.w, w1.w, acc[rr][5]));
            acc[rr][6] = fmaf(x1.z, w1.w, fmaf( x1.w, w0.w, acc[rr][6]));
        }
    }
    const int which = o >> 6, rem = o & 63;
    const int h = rem >> 3, d = rem & 7;
#pragma unroll
    for (int rr = 0; rr < 2; rr++) {
        const int bs = bs0 + row0 + rr;
        const int b = bs >> 6, s = bs & 63;
        size_t base = (((size_t)(b * NH + h) * Sn) + s) * 56 + d * 7;
        if (which == 0) {
            const float cs = 1.0f / (1048576.0f * 2.82842712474619f);
            g_Qf[base + 0] = acc[rr][0] * cs;
            g_Qf[base + 1] = acc[rr][1] * (0.5f * cs);
            g_Qf[base + 2] = acc[rr][2] * (0.5f * cs);
            g_Qf[base + 3] = acc[rr][3] * (2.0f * cs);
            g_Qf[base + 4] = acc[rr][4] * (2.0f * cs);
            g_Qf[base + 5] = acc[rr][5] * (2.0f * cs);
            g_Qf[base + 6] = acc[rr][6] * (2.0f * cs);
        } else {
            float* dst = (which == 1) ? g_Kf : g_Vf;
#pragma unroll
            for (int m = 0; m < 7; m++) dst[base + m] = acc[rr][m];
        }
    }
}

// ---------------------------------------------------------------------------
// K3: log-CPB bias.
// ---------------------------------------------------------------------------
__device__ __forceinline__ float signlog2(float x) {
    return copysignf(log2f(1.0f + fabsf(x)), x);
}
__global__ void k_bias(const float* __restrict__ w1, const float* __restrict__ b1,
                       const float* __restrict__ w2, const int* __restrict__ nsy_p) {
    int idx = blockIdx.x * blockDim.x + threadIdx.x;
    if (idx >= Sn * Sn) return;
    int i = idx >> 6, j = idx & 63;
    int ny = *nsy_p;
    float r0 = signlog2((float)(i / ny - j / ny));
    float r1 = signlog2((float)(i % ny - j % ny));
    float out[NH];
#pragma unroll
    for (int hh = 0; hh < NH; hh++) out[hh] = 0.f;
    for (int e = 0; e < En; e++) {
        float hv = fmaxf(fmaf(r0, w1[e], fmaf(r1, w1[En + e], b1[e])), 0.f);
#pragma unroll
        for (int hh = 0; hh < NH; hh++) out[hh] = fmaf(hv, w2[e * NH + hh], out[hh]);
    }
#pragma unroll
    for (int hh = 0; hh < NH; hh++) g_bias[hh * (Sn * Sn) + idx] = out[hh];
}

// ---------------------------------------------------------------------------
// K4: attention, 56-dim feature space. grid (64 bh, 4 i-chunks), 256 thr.
// Q staged via smem (vectorized) then held in registers; K/V float4 smem fill.
// ---------------------------------------------------------------------------
__global__ void k_attn() {
    const int bh = blockIdx.x;
    const int h = bh & (NH - 1);
    const int i0 = blockIdx.y * 16;
    __shared__ float Qs[16 * 60];
    __shared__ float Ks[64 * 60];
    __shared__ float Vs[64 * 60];
    __shared__ float Sc[16 * 65];
    const int t = threadIdx.x;

    {
        const float4* kg = (const float4*)(g_Kf + (size_t)bh * 64 * 56);
        const float4* vg = (const float4*)(g_Vf + (size_t)bh * 64 * 56);
        float4* ks4 = (float4*)Ks;
        float4* vs4 = (float4*)Vs;
#pragma unroll
        for (int idx = t; idx < 64 * 14; idx += 256) {
            int row = idx / 14, m = idx - row * 14;
            ks4[row * 15 + m] = kg[idx];
            vs4[row * 15 + m] = vg[idx];
        }
        const float4* qg = (const float4*)(g_Qf + ((size_t)bh * 64 + i0) * 56);
        float4* qs4 = (float4*)Qs;
        if (t < 16 * 14) {
            int row = t / 14, m = t - row * 14;
            qs4[row * 15 + m] = qg[t];
        }
    }
    __syncthreads();

    const int i_l = t >> 4, part = t & 15;
    const int i = i0 + i_l;

    float4 q4[14];
#pragma unroll
    for (int m = 0; m < 14; m++) q4[m] = ((const float4*)Qs)[i_l * 15 + m];

    const float* bias_row = g_bias + h * (Sn * Sn) + i * 64;
    float scv[4];
#pragma unroll
    for (int jj = 0; jj < 4; jj++) {
        int j = jj * 16 + part;
        float a = bias_row[j];
        const float4* kr = (const float4*)Ks + j * 15;
#pragma unroll
        for (int m = 0; m < 14; m++) {
            float4 kv = kr[m];
            a = fmaf(q4[m].x, kv.x, a);
            a = fmaf(q4[m].y, kv.y, a);
            a = fmaf(q4[m].z, kv.z, a);
            a = fmaf(q4[m].w, kv.w, a);
        }
        scv[jj] = a;
    }
    float mx = fmaxf(fmaxf(scv[0], scv[1]), fmaxf(scv[2], scv[3]));
#pragma unroll
    for (int off = 8; off; off >>= 1)
        mx = fmaxf(mx, __shfl_xor_sync(0xffffffffu, mx, off, 16));
    float e0 = __expf(scv[0] - mx), e1 = __expf(scv[1] - mx);
    float e2 = __expf(scv[2] - mx), e3 = __expf(scv[3] - mx);
    float sum = (e0 + e1) + (e2 + e3);
#pragma unroll
    for (int off = 8; off; off >>= 1)
        sum += __shfl_xor_sync(0xffffffffu, sum, off, 16);
    float inv = 1.0f / sum;
    Sc[i_l * 65 +  0 + part] = e0 * inv;
    Sc[i_l * 65 + 16 + part] = e1 * inv;
    Sc[i_l * 65 + 32 + part] = e2 * inv;
    Sc[i_l * 65 + 48 + part] = e3 * inv;
    __syncthreads();

    if (part < 14) {
        const int m0 = part * 4;
        float a0 = 0.f, a1 = 0.f, a2 = 0.f, a3 = 0.f;
        const float* sr = &Sc[i_l * 65];
#pragma unroll 8
        for (int j = 0; j < 64; j++) {
            float a = sr[j];
            float4 vv = *(const float4*)&Vs[j * 60 + m0];
            a0 = fmaf(a, vv.x, a0);
            a1 = fmaf(a, vv.y, a1);
            a2 = fmaf(a, vv.z, a2);
            a3 = fmaf(a, vv.w, a3);
        }
        float* og = g_O + ((size_t)bh * 64 + i) * 56 + m0;
        og[0] = a0; og[1] = a1; og[2] = a2; og[3] = a3;
    }
}

// ---------------------------------------------------------------------------
// K5: output spectral mixing FUSED with synthesis.
// grid (64, 2), 256 thr: compute phase = 8 grp (bs rows) x 32 o lanes, one
// thread owns one tile's G modes -> staged in smem -> warp-per-tile epilogue
// writes the 32x32 pixels with STG.128.
// ---------------------------------------------------------------------------
__global__ void k_out_synth(const float* __restrict__ wr, const float* __restrict__ wi,
                            float* __restrict__ out) {
    __shared__ float Fs[8 * 64 * 8];   // 16KB
    __shared__ float Gs[8 * 32 * 8];   // 8KB
    __shared__ float tc[32], ts[32];
    const int bs0 = blockIdx.x * 8;
    const int o0  = blockIdx.y * 32;
    const int t = threadIdx.x;

    if (t < 32) {
        float s, c;
        sincospif((float)t * (1.0f/16.0f), &s, &c);
        tc[t] = c; ts[t] = s;
    }
    for (int idx = t; idx < 8 * 64; idx += 256) Fs[idx * 8 + 1] = 0.f;
    for (int idx = t; idx < 8 * 64 * 7; idx += 256) {
        int r = idx / 448, rem = idx % 448;
        int c = rem / 7, m = rem % 7;
        int bsv = bs0 + r;
        int b = bsv >> 6, s = bsv & 63;
        float v = g_O[(((size_t)(b * NH + (c >> 3)) * Sn) + s) * 56 + (c & 7) * 7 + m];
        int slot = (m == 0) ? 0 : (m + 1);
        float sc = (m == 1 || m == 2) ? 0.5f : 1.0f;
        Fs[(r * 64 + c) * 8 + slot] = v * sc;
    }
    __syncthreads();

    const int o_l = t & 31, grp = t >> 5;
    const int o = o0 + o_l;

    float a0 = 0.f, a1 = 0.f, a2 = 0.f, a3 = 0.f, a4 = 0.f, a5 = 0.f, a6 = 0.f;
    const float4* wr4 = (const float4*)wr;
    const float4* wi4 = (const float4*)wi;
#pragma unroll 4
    for (int c = 0; c < 64; c++) {
        float4 x0 = *(const float4*)&Fs[(grp * 64 + c) * 8];
        float4 x1 = *(const float4*)&Fs[(grp * 64 + c) * 8 + 4];
        float4 w0 = wr4[c * Cn + o];
        float4 w1 = wi4[c * Cn + o];
        a0 = fmaf(x0.x, w0.x, a0);
        a1 = fmaf(x0.z, w0.z, fmaf(-x0.w, w1.z, a1));
        a2 = fmaf(x0.z, w1.z, fmaf( x0.w, w0.z, a2));
        a3 = fmaf(x1.x, w0.y, fmaf(-x1.y, w1.y, a3));
        a4 = fmaf(x1.x, w1.y, fmaf( x1.y, w0.y, a4));
        a5 = fmaf(x1.z, w0.w, fmaf(-x1.w, w1.w, a5));
        a6 = fmaf(x1.z, w1.w, fmaf( x1.w, w0.w, a6));
    }
    {
        float* g = &Gs[t * 8];
        g[0] = a0;
        g[2] = a1; g[3] = a2;
        g[4] = a3; g[5] = a4;
        g[6] = a5; g[7] = a6;
    }
    __syncthreads();

    // Epilogue: warp per tile; lane = (w-quad, h-strip); STG.128 stores.
    const int warp = t >> 5, lane = t & 31;
    const int w0q = (lane & 7) * 4;
    const int h0 = lane >> 3;
    const float inv = 1.0f / 1024.0f;
    for (int tl = warp; tl < 256; tl += 8) {
        const float* g = &Gs[tl * 8];
        float g00r = g[0], g10r = g[2], g10i = g[3];
        float g01r = g[4], g01i = g[5], g11r = g[6], g11i = g[7];
        float P0[4], Pc[4], Ps[4];
#pragma unroll
        for (int jw = 0; jw < 4; jw++) {
            float cw = tc[w0q + jw], sw = ts[w0q + jw];
            P0[jw] = (g00r + 2.0f * (g01r * cw - g01i * sw)) * inv;
            Pc[jw] = (g10r + 2.0f * (g11r * cw - g11i * sw)) * inv;
            Ps[jw] = (-g10i - 2.0f * (g11r * sw + g11i * cw)) * inv;
        }
        size_t tile = (size_t)(bs0 + (tl >> 5)) * 64 + o0 + (tl & 31);
        float4* dst = (float4*)(out + tile * 1024);
#pragma unroll
        for (int it = 0; it < 8; it++) {
            int hh = h0 + it * 4;
            float c = tc[hh], s = ts[hh];
            float4 v;
            v.x = fmaf(Pc[0], c, fmaf(Ps[0], s, P0[0]));
            v.y = fmaf(Pc[1], c, fmaf(Ps[1], s, P0[1]));
            v.z = fmaf(Pc[2], c, fmaf(Ps[2], s, P0[2]));
            v.w = fmaf(Pc[3], c, fmaf(Ps[3], s, P0[3]));
            dst[hh * 8 + (lane & 7)] = v;
        }
    }
}

// ---------------------------------------------------------------------------
extern "C" void kernel_launch(void* const* d_in, const int* in_sizes, int n_in,
                              void* d_out, int out_size) {
    const float* seq = (const float*)d_in[0];
    const float* wqr = (const float*)d_in[1];
    const float* wqi = (const float*)d_in[2];
    const float* wor = (const float*)d_in[3];
    const float* woi = (const float*)d_in[4];
    const float* w1  = (const float*)d_in[5];
    const float* b1  = (const float*)d_in[6];
    const float* w2  = (const float*)d_in[7];
    const int* nsy   = (const int*)d_in[9];
    float* out = (float*)d_out;

    k_bias<<<16, 256>>>(w1, b1, w2, nsy);
    k_modes<<<TILES / 8, 256>>>(seq);
    k_qkv_mix<<<dim3(32, 6), 256>>>(wqr, wqi);
    k_attn<<<dim3(Bn * NH, 4), 256>>>();
    k_out_synth<<<dim3(64, 2), 256>>>(wor, woi, out);
}

// round 4
// speedup vs baseline: 1.6417x; 1.1564x over previous
#include <cuda_runtime.h>
#include <math.h>

#define Bn   8
#define Sn   64
#define Cn   64
#define Hn   32
#define Wn   32
#define NH   8
#define HD   8
#define BS   (Bn*Sn)        // 512
#define TILES (BS*Cn)       // 32768
#define O3   (3*Cn)         // 192
#define En   64

#define MODE_BLOCKS (TILES/16)   // 2048 (2 tiles per warp, 8 warps)

__device__ float g_X[TILES*8];
__device__ float g_Qf[Bn*NH*Sn*56];
__device__ float g_Kf[Bn*NH*Sn*56];
__device__ float g_Vf[Bn*NH*Sn*56];
__device__ float g_bias[NH*Sn*Sn];
__device__ float g_O[Bn*NH*Sn*56];

__device__ __forceinline__ float signlog2(float x) {
    return copysignf(log2f(1.0f + fabsf(x)), x);
}

// ---------------------------------------------------------------------------
// K1: mode extraction (2 tiles per warp, MLP=16) + fused CPB-bias blocks.
// ---------------------------------------------------------------------------
__global__ void k_modes_bias(const float* __restrict__ x,
                             const float* __restrict__ w1, const float* __restrict__ b1,
                             const float* __restrict__ w2, const int* __restrict__ nsy_p) {
    if (blockIdx.x >= MODE_BLOCKS) {
        // ----- bias part: 16 blocks x 256 threads = 4096 (i,j) pairs -----
        int idx = (blockIdx.x - MODE_BLOCKS) * 256 + threadIdx.x;
        int i = idx >> 6, j = idx & 63;
        int ny = *nsy_p;
        float r0 = signlog2((float)(i / ny - j / ny));
        float r1 = signlog2((float)(i % ny - j % ny));
        float outv[NH];
#pragma unroll
        for (int hh = 0; hh < NH; hh++) outv[hh] = 0.f;
        for (int e = 0; e < En; e++) {
            float hv = fmaxf(fmaf(r0, w1[e], fmaf(r1, w1[En + e], b1[e])), 0.f);
#pragma unroll
            for (int hh = 0; hh < NH; hh++) outv[hh] = fmaf(hv, w2[e * NH + hh], outv[hh]);
        }
#pragma unroll
        for (int hh = 0; hh < NH; hh++) g_bias[hh * (Sn * Sn) + idx] = outv[hh];
        return;
    }
    // ----- modes part -----
    __shared__ float tc[32], ts[32];
    if (threadIdx.x < 32) {
        float s, c;
        sincospif((float)threadIdx.x * (1.0f/16.0f), &s, &c);
        tc[threadIdx.x] = c; ts[threadIdx.x] = s;
    }
    __syncthreads();
    const int warp = threadIdx.x >> 5, lane = threadIdx.x & 31;
    const int tile0 = blockIdx.x * 16 + warp * 2;
    const float4* p0 = (const float4*)(x + (size_t)tile0 * 1024) + lane;
    const float4* p1 = p0 + 256;
    const int w0 = (lane & 7) * 4;
    const int h0 = lane >> 3;

    float a0[4] = {0,0,0,0}, bc0[4] = {0,0,0,0}, bs0[4] = {0,0,0,0};
    float a1[4] = {0,0,0,0}, bc1[4] = {0,0,0,0}, bs1[4] = {0,0,0,0};
#pragma unroll
    for (int it = 0; it < 8; it++) {
        float4 v0 = p0[it * 32];
        float4 v1 = p1[it * 32];
        int hh = h0 + it * 4;
        float c = tc[hh], s = ts[hh];
        a0[0] += v0.x; bc0[0] = fmaf(v0.x, c, bc0[0]); bs0[0] = fmaf(v0.x, s, bs0[0]);
        a0[1] += v0.y; bc0[1] = fmaf(v0.y, c, bc0[1]); bs0[1] = fmaf(v0.y, s, bs0[1]);
        a0[2] += v0.z; bc0[2] = fmaf(v0.z, c, bc0[2]); bs0[2] = fmaf(v0.z, s, bs0[2]);
        a0[3] += v0.w; bc0[3] = fmaf(v0.w, c, bc0[3]); bs0[3] = fmaf(v0.w, s, bs0[3]);
        a1[0] += v1.x; bc1[0] = fmaf(v1.x, c, bc1[0]); bs1[0] = fmaf(v1.x, s, bs1[0]);
        a1[1] += v1.y; bc1[1] = fmaf(v1.y, c, bc1[1]); bs1[1] = fmaf(v1.y, s, bs1[1]);
        a1[2] += v1.z; bc1[2] = fmaf(v1.z, c, bc1[2]); bs1[2] = fmaf(v1.z, s, bs1[2]);
        a1[3] += v1.w; bc1[3] = fmaf(v1.w, c, bc1[3]); bs1[3] = fmaf(v1.w, s, bs1[3]);
    }
    float r0v[7] = {0,0,0,0,0,0,0}, r1v[7] = {0,0,0,0,0,0,0};
#pragma unroll
    for (int j = 0; j < 4; j++) {
        float cw = tc[w0 + j], sw = ts[w0 + j];
        r0v[0] += a0[j];  r0v[1] += bc0[j];  r0v[2] += bs0[j];
        r0v[3] = fmaf(a0[j], cw, r0v[3]);  r0v[4] = fmaf(a0[j], sw, r0v[4]);
        r0v[5] += bc0[j] * cw - bs0[j] * sw;
        r0v[6] += bs0[j] * cw + bc0[j] * sw;
        r1v[0] += a1[j];  r1v[1] += bc1[j];  r1v[2] += bs1[j];
        r1v[3] = fmaf(a1[j], cw, r1v[3]);  r1v[4] = fmaf(a1[j], sw, r1v[4]);
        r1v[5] += bc1[j] * cw - bs1[j] * sw;
        r1v[6] += bs1[j] * cw + bc1[j] * sw;
    }
#pragma unroll
    for (int k = 0; k < 7; k++) {
#pragma unroll
        for (int off = 16; off; off >>= 1) {
            r0v[k] += __shfl_xor_sync(0xffffffffu, r0v[k], off);
            r1v[k] += __shfl_xor_sync(0xffffffffu, r1v[k], off);
        }
    }
    if (lane == 0) {
        float* d0 = g_X + (size_t)tile0 * 8;
        d0[0] = r0v[0]; d0[1] = 0.f;
        d0[2] = r0v[1]; d0[3] = -r0v[2];
        d0[4] = r0v[3]; d0[5] = -r0v[4];
        d0[6] = r0v[5]; d0[7] = -r0v[6];
        float* d1 = d0 + 8;
        d1[0] = r1v[0]; d1[1] = 0.f;
        d1[2] = r1v[1]; d1[3] = -r1v[2];
        d1[4] = r1v[3]; d1[5] = -r1v[4];
        d1[6] = r1v[5]; d1[7] = -r1v[6];
    }
}

// ---------------------------------------------------------------------------
// K2: QKV spectral mixing. Block = 8 bs x 32 o; 256 thr = 8 grp x 32 o_l,
// grp owns 1 bs row. grid (64,6) = 384 blocks.
// ---------------------------------------------------------------------------
__global__ void k_qkv_mix(const float* __restrict__ wr, const float* __restrict__ wi) {
    __shared__ float Xs[8 * 64 * 8];  // 16KB
    const int bs0 = blockIdx.x * 8;
    const int o0  = blockIdx.y * 32;
    const int t = threadIdx.x;
    {
        const float4* gx = (const float4*)(g_X + (size_t)bs0 * 512);
        float4* xs4 = (float4*)Xs;
#pragma unroll
        for (int idx = t; idx < 8 * 64 * 2; idx += 256)
            xs4[idx] = gx[idx];
    }
    __syncthreads();

    const int o_l = t & 31, grp = t >> 5;
    const int o = o0 + o_l;

    float acc[7] = {0,0,0,0,0,0,0};
    const float4* wr4 = (const float4*)wr;
    const float4* wi4 = (const float4*)wi;
#pragma unroll 4
    for (int c = 0; c < 64; c++) {
        float4 w0 = wr4[c * O3 + o];
        float4 w1 = wi4[c * O3 + o];
        float4 x0 = *(const float4*)&Xs[(grp * 64 + c) * 8];
        float4 x1 = *(const float4*)&Xs[(grp * 64 + c) * 8 + 4];
        acc[0] = fmaf(x0.x, w0.x, acc[0]);
        acc[1] = fmaf(x0.z, w0.z, fmaf(-x0.w, w1.z, acc[1]));
        acc[2] = fmaf(x0.z, w1.z, fmaf( x0.w, w0.z, acc[2]));
        acc[3] = fmaf(x1.x, w0.y, fmaf(-x1.y, w1.y, acc[3]));
        acc[4] = fmaf(x1.x, w1.y, fmaf( x1.y, w0.y, acc[4]));
        acc[5] = fmaf(x1.z, w0.w, fmaf(-x1.w, w1.w, acc[5]));
        acc[6] = fmaf(x1.z, w1.w, fmaf( x1.w, w0.w, acc[6]));
    }
    const int which = o >> 6, rem = o & 63;
    const int h = rem >> 3, d = rem & 7;
    const int bs = bs0 + grp;
    const int b = bs >> 6, s = bs & 63;
    size_t base = (((size_t)(b * NH + h) * Sn) + s) * 56 + d * 7;
    if (which == 0) {
        const float cs = 1.0f / (1048576.0f * 2.82842712474619f);
        g_Qf[base + 0] = acc[0] * cs;
        g_Qf[base + 1] = acc[1] * (0.5f * cs);
        g_Qf[base + 2] = acc[2] * (0.5f * cs);
        g_Qf[base + 3] = acc[3] * (2.0f * cs);
        g_Qf[base + 4] = acc[4] * (2.0f * cs);
        g_Qf[base + 5] = acc[5] * (2.0f * cs);
        g_Qf[base + 6] = acc[6] * (2.0f * cs);
    } else {
        float* dst = (which == 1) ? g_Kf : g_Vf;
#pragma unroll
        for (int m = 0; m < 7; m++) dst[base + m] = acc[m];
    }
}

// ---------------------------------------------------------------------------
// K4: attention. grid (64 bh, 8 i-chunks of 8), 128 thr = 8 i x 16 part.
// ---------------------------------------------------------------------------
__global__ void k_attn() {
    const int bh = blockIdx.x;
    const int h = bh & (NH - 1);
    const int i0 = blockIdx.y * 8;
    __shared__ float Qs[8 * 60];
    __shared__ float Ks[64 * 60];
    __shared__ float Vs[64 * 60];
    __shared__ float Sc[8 * 65];
    const int t = threadIdx.x;

    {
        const float4* kg = (const float4*)(g_Kf + (size_t)bh * 64 * 56);
        const float4* vg = (const float4*)(g_Vf + (size_t)bh * 64 * 56);
        float4* ks4 = (float4*)Ks;
        float4* vs4 = (float4*)Vs;
#pragma unroll
        for (int idx = t; idx < 64 * 14; idx += 128) {
            int row = idx / 14, m = idx - row * 14;
            ks4[row * 15 + m] = kg[idx];
            vs4[row * 15 + m] = vg[idx];
        }
        const float4* qg = (const float4*)(g_Qf + ((size_t)bh * 64 + i0) * 56);
        float4* qs4 = (float4*)Qs;
        if (t < 8 * 14) {
            int row = t / 14, m = t - row * 14;
            qs4[row * 15 + m] = qg[t];
        }
    }
    __syncthreads();

    const int i_l = t >> 4, part = t & 15;
    const int i = i0 + i_l;

    float4 q4[14];
#pragma unroll
    for (int m = 0; m < 14; m++) q4[m] = ((const float4*)Qs)[i_l * 15 + m];

    const float* bias_row = g_bias + h * (Sn * Sn) + i * 64;
    float scv[4];
#pragma unroll
    for (int jj = 0; jj < 4; jj++) {
        int j = jj * 16 + part;
        float a = bias_row[j];
        const float4* kr = (const float4*)Ks + j * 15;
#pragma unroll
        for (int m = 0; m < 14; m++) {
            float4 kv = kr[m];
            a = fmaf(q4[m].x, kv.x, a);
            a = fmaf(q4[m].y, kv.y, a);
            a = fmaf(q4[m].z, kv.z, a);
            a = fmaf(q4[m].w, kv.w, a);
        }
        scv[jj] = a;
    }
    float mx = fmaxf(fmaxf(scv[0], scv[1]), fmaxf(scv[2], scv[3]));
#pragma unroll
    for (int off = 8; off; off >>= 1)
        mx = fmaxf(mx, __shfl_xor_sync(0xffffffffu, mx, off, 16));
    float e0 = __expf(scv[0] - mx), e1 = __expf(scv[1] - mx);
    float e2 = __expf(scv[2] - mx), e3 = __expf(scv[3] - mx);
    float sum = (e0 + e1) + (e2 + e3);
#pragma unroll
    for (int off = 8; off; off >>= 1)
        sum += __shfl_xor_sync(0xffffffffu, sum, off, 16);
    float inv = 1.0f / sum;
    Sc[i_l * 65 +  0 + part] = e0 * inv;
    Sc[i_l * 65 + 16 + part] = e1 * inv;
    Sc[i_l * 65 + 32 + part] = e2 * inv;
    Sc[i_l * 65 + 48 + part] = e3 * inv;
    __syncthreads();

    if (part < 14) {
        const int m0 = part * 4;
        float a0 = 0.f, a1 = 0.f, a2 = 0.f, a3 = 0.f;
        const float* sr = &Sc[i_l * 65];
#pragma unroll 8
        for (int j = 0; j < 64; j++) {
            float a = sr[j];
            float4 vv = *(const float4*)&Vs[j * 60 + m0];
            a0 = fmaf(a, vv.x, a0);
            a1 = fmaf(a, vv.y, a1);
            a2 = fmaf(a, vv.z, a2);
            a3 = fmaf(a, vv.w, a3);
        }
        float* og = g_O + ((size_t)bh * 64 + i) * 56 + m0;
        og[0] = a0; og[1] = a1; og[2] = a2; og[3] = a3;
    }
}

// ---------------------------------------------------------------------------
// K5: output mixing + synthesis. grid (128, 2), 256 thr.
// GEMM: 8 grp = 4 bs-rows x 2 c-halves (partial G -> smem, summed in epilogue).
// Epilogue: 8 warps x 16 tiles, STG.128.
// ---------------------------------------------------------------------------
__global__ void k_out_synth(const float* __restrict__ wr, const float* __restrict__ wi,
                            float* __restrict__ out) {
    __shared__ float Fs[4 * 64 * 8];   // 8KB
    __shared__ float Gs[8 * 32 * 8];   // 8KB (partials: [grp][o][8])
    __shared__ float tc[32], ts[32];
    const int bs0 = blockIdx.x * 4;
    const int o0  = blockIdx.y * 32;
    const int t = threadIdx.x;

    if (t < 32) {
        float s, c;
        sincospif((float)t * (1.0f/16.0f), &s, &c);
        tc[t] = c; ts[t] = s;
    }
    for (int idx = t; idx < 4 * 64; idx += 256) Fs[idx * 8 + 1] = 0.f;
    for (int idx = t; idx < 4 * 64 * 7; idx += 256) {
        int r = idx / 448, rem = idx % 448;
        int c = rem / 7, m = rem % 7;
        int bsv = bs0 + r;
        int b = bsv >> 6, s = bsv & 63;
        float v = g_O[(((size_t)(b * NH + (c >> 3)) * Sn) + s) * 56 + (c & 7) * 7 + m];
        int slot = (m == 0) ? 0 : (m + 1);
        float sc = (m == 1 || m == 2) ? 0.5f : 1.0f;
        Fs[(r * 64 + c) * 8 + slot] = v * sc;
    }
    __syncthreads();

    const int o_l = t & 31, grp = t >> 5;
    const int row = grp >> 1, half = grp & 1;
    const int o = o0 + o_l;
    const int c0 = half * 32;

    float a0 = 0.f, a1 = 0.f, a2 = 0.f, a3 = 0.f, a4 = 0.f, a5 = 0.f, a6 = 0.f;
    const float4* wr4 = (const float4*)wr;
    const float4* wi4 = (const float4*)wi;
#pragma unroll 4
    for (int cc = 0; cc < 32; cc++) {
        int c = c0 + cc;
        float4 x0 = *(const float4*)&Fs[(row * 64 + c) * 8];
        float4 x1 = *(const float4*)&Fs[(row * 64 + c) * 8 + 4];
        float4 w0 = wr4[c * Cn + o];
        float4 w1 = wi4[c * Cn + o];
        a0 = fmaf(x0.x, w0.x, a0);
        a1 = fmaf(x0.z, w0.z, fmaf(-x0.w, w1.z, a1));
        a2 = fmaf(x0.z, w1.z, fmaf( x0.w, w0.z, a2));
        a3 = fmaf(x1.x, w0.y, fmaf(-x1.y, w1.y, a3));
        a4 = fmaf(x1.x, w1.y, fmaf( x1.y, w0.y, a4));
        a5 = fmaf(x1.z, w0.w, fmaf(-x1.w, w1.w, a5));
        a6 = fmaf(x1.z, w1.w, fmaf( x1.w, w0.w, a6));
    }
    {
        float* g = &Gs[t * 8];
        g[0] = a0; g[1] = 0.f;
        g[2] = a1; g[3] = a2;
        g[4] = a3; g[5] = a4;
        g[6] = a5; g[7] = a6;
    }
    __syncthreads();

    // Epilogue: 8 warps x 16 tiles (tl in 0..127 -> row=tl>>5, o_l=tl&31).
    const int warp = t >> 5, lane = t & 31;
    const int w0q = (lane & 7) * 4;
    const int h0 = lane >> 3;
    const float inv = 1.0f / 1024.0f;
    for (int tl = warp; tl < 128; tl += 8) {
        const int trow = tl >> 5, tol = tl & 31;
        const float* gA = &Gs[((trow * 2) * 32 + tol) * 8];
        const float* gB = &Gs[((trow * 2 + 1) * 32 + tol) * 8];
        float g00r = gA[0] + gB[0];
        float g10r = gA[2] + gB[2], g10i = gA[3] + gB[3];
        float g01r = gA[4] + gB[4], g01i = gA[5] + gB[5];
        float g11r = gA[6] + gB[6], g11i = gA[7] + gB[7];
        float P0[4], Pc[4], Ps[4];
#pragma unroll
        for (int jw = 0; jw < 4; jw++) {
            float cw = tc[w0q + jw], sw = ts[w0q + jw];
            P0[jw] = (g00r + 2.0f * (g01r * cw - g01i * sw)) * inv;
            Pc[jw] = (g10r + 2.0f * (g11r * cw - g11i * sw)) * inv;
            Ps[jw] = (-g10i - 2.0f * (g11r * sw + g11i * cw)) * inv;
        }
        size_t tile = (size_t)(bs0 + trow) * 64 + o0 + tol;
        float4* dst = (float4*)(out + tile * 1024);
#pragma unroll
        for (int it = 0; it < 8; it++) {
            int hh = h0 + it * 4;
            float c = tc[hh], s = ts[hh];
            float4 v;
            v.x = fmaf(Pc[0], c, fmaf(Ps[0], s, P0[0]));
            v.y = fmaf(Pc[1], c, fmaf(Ps[1], s, P0[1]));
            v.z = fmaf(Pc[2], c, fmaf(Ps[2], s, P0[2]));
            v.w = fmaf(Pc[3], c, fmaf(Ps[3], s, P0[3]));
            dst[hh * 8 + (lane & 7)] = v;
        }
    }
}

// ---------------------------------------------------------------------------
extern "C" void kernel_launch(void* const* d_in, const int* in_sizes, int n_in,
                              void* d_out, int out_size) {
    const float* seq = (const float*)d_in[0];
    const float* wqr = (const float*)d_in[1];
    const float* wqi = (const float*)d_in[2];
    const float* wor = (const float*)d_in[3];
    const float* woi = (const float*)d_in[4];
    const float* w1  = (const float*)d_in[5];
    const float* b1  = (const float*)d_in[6];
    const float* w2  = (const float*)d_in[7];
    const int* nsy   = (const int*)d_in[9];
    float* out = (float*)d_out;

    k_modes_bias<<<MODE_BLOCKS + 16, 256>>>(seq, w1, b1, w2, nsy);
    k_qkv_mix<<<dim3(64, 6), 256>>>(wqr, wqi);
    k_attn<<<dim3(Bn * NH, 8), 128>>>();
    k_out_synth<<<dim3(128, 2), 256>>>(wor, woi, out);
}

// round 5
// speedup vs baseline: 1.8926x; 1.1528x over previous
#include <cuda_runtime.h>
#include <math.h>

#define Bn   8
#define Sn   64
#define Cn   64
#define Hn   32
#define Wn   32
#define NH   8
#define HD   8
#define BS   (Bn*Sn)        // 512
#define TILES (BS*Cn)       // 32768
#define O3   (3*Cn)         // 192
#define En   64

#define MODE_BLOCKS (TILES/16)   // 2048 (2 tiles per warp, 8 warps)

__device__ float g_X[TILES*8];
__device__ float g_Qf[Bn*NH*Sn*56];
__device__ float g_Kf[Bn*NH*Sn*56];
__device__ float g_Vf[Bn*NH*Sn*56];
__device__ float g_bias[NH*Sn*Sn];
__device__ float g_O[Bn*NH*Sn*56];

__device__ __forceinline__ float signlog2(float x) {
    return copysignf(log2f(1.0f + fabsf(x)), x);
}

// ---------------------------------------------------------------------------
// K1: mode extraction (2 tiles per warp, MLP=16, streaming loads) + CPB bias.
// ---------------------------------------------------------------------------
__global__ void k_modes_bias(const float* __restrict__ x,
                             const float* __restrict__ w1, const float* __restrict__ b1,
                             const float* __restrict__ w2, const int* __restrict__ nsy_p) {
    if (blockIdx.x >= MODE_BLOCKS) {
        int idx = (blockIdx.x - MODE_BLOCKS) * 256 + threadIdx.x;
        int i = idx >> 6, j = idx & 63;
        int ny = *nsy_p;
        float r0 = signlog2((float)(i / ny - j / ny));
        float r1 = signlog2((float)(i % ny - j % ny));
        float outv[NH];
#pragma unroll
        for (int hh = 0; hh < NH; hh++) outv[hh] = 0.f;
        for (int e = 0; e < En; e++) {
            float hv = fmaxf(fmaf(r0, w1[e], fmaf(r1, w1[En + e], b1[e])), 0.f);
#pragma unroll
            for (int hh = 0; hh < NH; hh++) outv[hh] = fmaf(hv, w2[e * NH + hh], outv[hh]);
        }
#pragma unroll
        for (int hh = 0; hh < NH; hh++) g_bias[hh * (Sn * Sn) + idx] = outv[hh];
        return;
    }
    __shared__ float tc[32], ts[32];
    if (threadIdx.x < 32) {
        float s, c;
        sincospif((float)threadIdx.x * (1.0f/16.0f), &s, &c);
        tc[threadIdx.x] = c; ts[threadIdx.x] = s;
    }
    __syncthreads();
    const int warp = threadIdx.x >> 5, lane = threadIdx.x & 31;
    const int tile0 = blockIdx.x * 16 + warp * 2;
    const float4* p0 = (const float4*)(x + (size_t)tile0 * 1024) + lane;
    const float4* p1 = p0 + 256;
    const int w0 = (lane & 7) * 4;
    const int h0 = lane >> 3;

    float a0[4] = {0,0,0,0}, bc0[4] = {0,0,0,0}, bs0[4] = {0,0,0,0};
    float a1[4] = {0,0,0,0}, bc1[4] = {0,0,0,0}, bs1[4] = {0,0,0,0};
#pragma unroll
    for (int it = 0; it < 8; it++) {
        float4 v0 = __ldcs(&p0[it * 32]);
        float4 v1 = __ldcs(&p1[it * 32]);
        int hh = h0 + it * 4;
        float c = tc[hh], s = ts[hh];
        a0[0] += v0.x; bc0[0] = fmaf(v0.x, c, bc0[0]); bs0[0] = fmaf(v0.x, s, bs0[0]);
        a0[1] += v0.y; bc0[1] = fmaf(v0.y, c, bc0[1]); bs0[1] = fmaf(v0.y, s, bs0[1]);
        a0[2] += v0.z; bc0[2] = fmaf(v0.z, c, bc0[2]); bs0[2] = fmaf(v0.z, s, bs0[2]);
        a0[3] += v0.w; bc0[3] = fmaf(v0.w, c, bc0[3]); bs0[3] = fmaf(v0.w, s, bs0[3]);
        a1[0] += v1.x; bc1[0] = fmaf(v1.x, c, bc1[0]); bs1[0] = fmaf(v1.x, s, bs1[0]);
        a1[1] += v1.y; bc1[1] = fmaf(v1.y, c, bc1[1]); bs1[1] = fmaf(v1.y, s, bs1[1]);
        a1[2] += v1.z; bc1[2] = fmaf(v1.z, c, bc1[2]); bs1[2] = fmaf(v1.z, s, bs1[2]);
        a1[3] += v1.w; bc1[3] = fmaf(v1.w, c, bc1[3]); bs1[3] = fmaf(v1.w, s, bs1[3]);
    }
    float r0v[7] = {0,0,0,0,0,0,0}, r1v[7] = {0,0,0,0,0,0,0};
#pragma unroll
    for (int j = 0; j < 4; j++) {
        float cw = tc[w0 + j], sw = ts[w0 + j];
        r0v[0] += a0[j];  r0v[1] += bc0[j];  r0v[2] += bs0[j];
        r0v[3] = fmaf(a0[j], cw, r0v[3]);  r0v[4] = fmaf(a0[j], sw, r0v[4]);
        r0v[5] += bc0[j] * cw - bs0[j] * sw;
        r0v[6] += bs0[j] * cw + bc0[j] * sw;
        r1v[0] += a1[j];  r1v[1] += bc1[j];  r1v[2] += bs1[j];
        r1v[3] = fmaf(a1[j], cw, r1v[3]);  r1v[4] = fmaf(a1[j], sw, r1v[4]);
        r1v[5] += bc1[j] * cw - bs1[j] * sw;
        r1v[6] += bs1[j] * cw + bc1[j] * sw;
    }
#pragma unroll
    for (int k = 0; k < 7; k++) {
#pragma unroll
        for (int off = 16; off; off >>= 1) {
            r0v[k] += __shfl_xor_sync(0xffffffffu, r0v[k], off);
            r1v[k] += __shfl_xor_sync(0xffffffffu, r1v[k], off);
        }
    }
    if (lane == 0) {
        float* d0 = g_X + (size_t)tile0 * 8;
        d0[0] = r0v[0]; d0[1] = 0.f;
        d0[2] = r0v[1]; d0[3] = -r0v[2];
        d0[4] = r0v[3]; d0[5] = -r0v[4];
        d0[6] = r0v[5]; d0[7] = -r0v[6];
        float* d1 = d0 + 8;
        d1[0] = r1v[0]; d1[1] = 0.f;
        d1[2] = r1v[1]; d1[3] = -r1v[2];
        d1[4] = r1v[3]; d1[5] = -r1v[4];
        d1[6] = r1v[5]; d1[7] = -r1v[6];
    }
}

// ---------------------------------------------------------------------------
// K2: QKV spectral mixing. Block = 8 bs x 32 o; grid (64,6).
// ---------------------------------------------------------------------------
__global__ void k_qkv_mix(const float* __restrict__ wr, const float* __restrict__ wi) {
    __shared__ float Xs[8 * 64 * 8];  // 16KB
    const int bs0 = blockIdx.x * 8;
    const int o0  = blockIdx.y * 32;
    const int t = threadIdx.x;
    {
        const float4* gx = (const float4*)(g_X + (size_t)bs0 * 512);
        float4* xs4 = (float4*)Xs;
#pragma unroll
        for (int idx = t; idx < 8 * 64 * 2; idx += 256)
            xs4[idx] = gx[idx];
    }
    __syncthreads();

    const int o_l = t & 31, grp = t >> 5;
    const int o = o0 + o_l;

    float acc[7] = {0,0,0,0,0,0,0};
    const float4* wr4 = (const float4*)wr;
    const float4* wi4 = (const float4*)wi;
#pragma unroll 4
    for (int c = 0; c < 64; c++) {
        float4 w0 = wr4[c * O3 + o];
        float4 w1 = wi4[c * O3 + o];
        float4 x0 = *(const float4*)&Xs[(grp * 64 + c) * 8];
        float4 x1 = *(const float4*)&Xs[(grp * 64 + c) * 8 + 4];
        acc[0] = fmaf(x0.x, w0.x, acc[0]);
        acc[1] = fmaf(x0.z, w0.z, fmaf(-x0.w, w1.z, acc[1]));
        acc[2] = fmaf(x0.z, w1.z, fmaf( x0.w, w0.z, acc[2]));
        acc[3] = fmaf(x1.x, w0.y, fmaf(-x1.y, w1.y, acc[3]));
        acc[4] = fmaf(x1.x, w1.y, fmaf( x1.y, w0.y, acc[4]));
        acc[5] = fmaf(x1.z, w0.w, fmaf(-x1.w, w1.w, acc[5]));
        acc[6] = fmaf(x1.z, w1.w, fmaf( x1.w, w0.w, acc[6]));
    }
    const int which = o >> 6, rem = o & 63;
    const int h = rem >> 3, d = rem & 7;
    const int bs = bs0 + grp;
    const int b = bs >> 6, s = bs & 63;
    size_t base = (((size_t)(b * NH + h) * Sn) + s) * 56 + d * 7;
    if (which == 0) {
        const float cs = 1.0f / (1048576.0f * 2.82842712474619f);
        g_Qf[base + 0] = acc[0] * cs;
        g_Qf[base + 1] = acc[1] * (0.5f * cs);
        g_Qf[base + 2] = acc[2] * (0.5f * cs);
        g_Qf[base + 3] = acc[3] * (2.0f * cs);
        g_Qf[base + 4] = acc[4] * (2.0f * cs);
        g_Qf[base + 5] = acc[5] * (2.0f * cs);
        g_Qf[base + 6] = acc[6] * (2.0f * cs);
    } else {
        float* dst = (which == 1) ? g_Kf : g_Vf;
#pragma unroll
        for (int m = 0; m < 7; m++) dst[base + m] = acc[m];
    }
}

// ---------------------------------------------------------------------------
// K4: attention. grid (64 bh, 8 i-chunks of 8), 128 thr.
// ---------------------------------------------------------------------------
__global__ void k_attn() {
    const int bh = blockIdx.x;
    const int h = bh & (NH - 1);
    const int i0 = blockIdx.y * 8;
    __shared__ float Qs[8 * 60];
    __shared__ float Ks[64 * 60];
    __shared__ float Vs[64 * 60];
    __shared__ float Sc[8 * 65];
    const int t = threadIdx.x;

    {
        const float4* kg = (const float4*)(g_Kf + (size_t)bh * 64 * 56);
        const float4* vg = (const float4*)(g_Vf + (size_t)bh * 64 * 56);
        float4* ks4 = (float4*)Ks;
        float4* vs4 = (float4*)Vs;
#pragma unroll
        for (int idx = t; idx < 64 * 14; idx += 128) {
            int row = idx / 14, m = idx - row * 14;
            ks4[row * 15 + m] = kg[idx];
            vs4[row * 15 + m] = vg[idx];
        }
        const float4* qg = (const float4*)(g_Qf + ((size_t)bh * 64 + i0) * 56);
        float4* qs4 = (float4*)Qs;
        if (t < 8 * 14) {
            int row = t / 14, m = t - row * 14;
            qs4[row * 15 + m] = qg[t];
        }
    }
    __syncthreads();

    const int i_l = t >> 4, part = t & 15;
    const int i = i0 + i_l;

    float4 q4[14];
#pragma unroll
    for (int m = 0; m < 14; m++) q4[m] = ((const float4*)Qs)[i_l * 15 + m];

    const float* bias_row = g_bias + h * (Sn * Sn) + i * 64;
    float scv[4];
#pragma unroll
    for (int jj = 0; jj < 4; jj++) {
        int j = jj * 16 + part;
        float a = bias_row[j];
        const float4* kr = (const float4*)Ks + j * 15;
#pragma unroll
        for (int m = 0; m < 14; m++) {
            float4 kv = kr[m];
            a = fmaf(q4[m].x, kv.x, a);
            a = fmaf(q4[m].y, kv.y, a);
            a = fmaf(q4[m].z, kv.z, a);
            a = fmaf(q4[m].w, kv.w, a);
        }
        scv[jj] = a;
    }
    float mx = fmaxf(fmaxf(scv[0], scv[1]), fmaxf(scv[2], scv[3]));
#pragma unroll
    for (int off = 8; off; off >>= 1)
        mx = fmaxf(mx, __shfl_xor_sync(0xffffffffu, mx, off, 16));
    float e0 = __expf(scv[0] - mx), e1 = __expf(scv[1] - mx);
    float e2 = __expf(scv[2] - mx), e3 = __expf(scv[3] - mx);
    float sum = (e0 + e1) + (e2 + e3);
#pragma unroll
    for (int off = 8; off; off >>= 1)
        sum += __shfl_xor_sync(0xffffffffu, sum, off, 16);
    float inv = 1.0f / sum;
    Sc[i_l * 65 +  0 + part] = e0 * inv;
    Sc[i_l * 65 + 16 + part] = e1 * inv;
    Sc[i_l * 65 + 32 + part] = e2 * inv;
    Sc[i_l * 65 + 48 + part] = e3 * inv;
    __syncthreads();

    if (part < 14) {
        const int m0 = part * 4;
        float a0 = 0.f, a1 = 0.f, a2 = 0.f, a3 = 0.f;
        const float* sr = &Sc[i_l * 65];
#pragma unroll 8
        for (int j = 0; j < 64; j++) {
            float a = sr[j];
            float4 vv = *(const float4*)&Vs[j * 60 + m0];
            a0 = fmaf(a, vv.x, a0);
            a1 = fmaf(a, vv.y, a1);
            a2 = fmaf(a, vv.z, a2);
            a3 = fmaf(a, vv.w, a3);
        }
        float* og = g_O + ((size_t)bh * 64 + i) * 56 + m0;
        og[0] = a0; og[1] = a1; og[2] = a2; og[3] = a3;
    }
}

// ---------------------------------------------------------------------------
// K5: output mixing + synthesis. grid (256, 2) = 512 blocks, 256 thr.
// Block = 2 bs-rows x 32 o. GEMM: 8 grp = 2 rows x 4 c-quarters (16 c each).
// Epilogue: 8 warps x 8 tiles, sum 4 partials, STG.128 streaming.
// ---------------------------------------------------------------------------
__global__ void k_out_synth(const float* __restrict__ wr, const float* __restrict__ wi,
                            float* __restrict__ out) {
    __shared__ float Fs[2 * 64 * 8];   // 4KB
    __shared__ float Gs[8 * 32 * 8];   // 8KB  [grp][o][8]
    __shared__ float tc[32], ts[32];
    const int bs0 = blockIdx.x * 2;
    const int o0  = blockIdx.y * 32;
    const int t = threadIdx.x;

    if (t < 32) {
        float s, c;
        sincospif((float)t * (1.0f/16.0f), &s, &c);
        tc[t] = c; ts[t] = s;
    }
    if (t < 2 * 64) Fs[t * 8 + 1] = 0.f;
    for (int idx = t; idx < 2 * 64 * 7; idx += 256) {
        int r = idx / 448, rem = idx % 448;
        int c = rem / 7, m = rem % 7;
        int bsv = bs0 + r;
        int b = bsv >> 6, s = bsv & 63;
        float v = g_O[(((size_t)(b * NH + (c >> 3)) * Sn) + s) * 56 + (c & 7) * 7 + m];
        int slot = (m == 0) ? 0 : (m + 1);
        float sc = (m == 1 || m == 2) ? 0.5f : 1.0f;
        Fs[(r * 64 + c) * 8 + slot] = v * sc;
    }
    __syncthreads();

    const int o_l = t & 31, grp = t >> 5;
    const int row = grp >> 2, quarter = grp & 3;
    const int o = o0 + o_l;
    const int c0 = quarter * 16;

    float a0 = 0.f, a1 = 0.f, a2 = 0.f, a3 = 0.f, a4 = 0.f, a5 = 0.f, a6 = 0.f;
    const float4* wr4 = (const float4*)wr;
    const float4* wi4 = (const float4*)wi;
#pragma unroll 4
    for (int cc = 0; cc < 16; cc++) {
        int c = c0 + cc;
        float4 x0 = *(const float4*)&Fs[(row * 64 + c) * 8];
        float4 x1 = *(const float4*)&Fs[(row * 64 + c) * 8 + 4];
        float4 w0 = wr4[c * Cn + o];
        float4 w1 = wi4[c * Cn + o];
        a0 = fmaf(x0.x, w0.x, a0);
        a1 = fmaf(x0.z, w0.z, fmaf(-x0.w, w1.z, a1));
        a2 = fmaf(x0.z, w1.z, fmaf( x0.w, w0.z, a2));
        a3 = fmaf(x1.x, w0.y, fmaf(-x1.y, w1.y, a3));
        a4 = fmaf(x1.x, w1.y, fmaf( x1.y, w0.y, a4));
        a5 = fmaf(x1.z, w0.w, fmaf(-x1.w, w1.w, a5));
        a6 = fmaf(x1.z, w1.w, fmaf( x1.w, w0.w, a6));
    }
    {
        float* g = &Gs[t * 8];
        g[0] = a0; g[1] = 0.f;
        g[2] = a1; g[3] = a2;
        g[4] = a3; g[5] = a4;
        g[6] = a5; g[7] = a6;
    }
    __syncthreads();

    // Epilogue: 64 tiles, 8 warps -> 8 tiles/warp; sum 4 quarter-partials.
    const int warp = t >> 5, lane = t & 31;
    const int w0q = (lane & 7) * 4;
    const int h0 = lane >> 3;
    const float inv = 1.0f / 1024.0f;
    for (int tl = warp; tl < 64; tl += 8) {
        const int trow = tl >> 5, tol = tl & 31;
        float g00r = 0.f, g10r = 0.f, g10i = 0.f;
        float g01r = 0.f, g01i = 0.f, g11r = 0.f, g11i = 0.f;
#pragma unroll
        for (int qq = 0; qq < 4; qq++) {
            const float* gp = &Gs[((trow * 4 + qq) * 32 + tol) * 8];
            g00r += gp[0];
            g10r += gp[2]; g10i += gp[3];
            g01r += gp[4]; g01i += gp[5];
            g11r += gp[6]; g11i += gp[7];
        }
        float P0[4], Pc[4], Ps[4];
#pragma unroll
        for (int jw = 0; jw < 4; jw++) {
            float cw = tc[w0q + jw], sw = ts[w0q + jw];
            P0[jw] = (g00r + 2.0f * (g01r * cw - g01i * sw)) * inv;
            Pc[jw] = (g10r + 2.0f * (g11r * cw - g11i * sw)) * inv;
            Ps[jw] = (-g10i - 2.0f * (g11r * sw + g11i * cw)) * inv;
        }
        size_t tile = (size_t)(bs0 + trow) * 64 + o0 + tol;
        float4* dst = (float4*)(out + tile * 1024);
#pragma unroll
        for (int it = 0; it < 8; it++) {
            int hh = h0 + it * 4;
            float c = tc[hh], s = ts[hh];
            float4 v;
            v.x = fmaf(Pc[0], c, fmaf(Ps[0], s, P0[0]));
            v.y = fmaf(Pc[1], c, fmaf(Ps[1], s, P0[1]));
            v.z = fmaf(Pc[2], c, fmaf(Ps[2], s, P0[2]));
            v.w = fmaf(Pc[3], c, fmaf(Ps[3], s, P0[3]));
            __stcs(&dst[hh * 8 + (lane & 7)], v);
        }
    }
}

// ---------------------------------------------------------------------------
extern "C" void kernel_launch(void* const* d_in, const int* in_sizes, int n_in,
                              void* d_out, int out_size) {
    const float* seq = (const float*)d_in[0];
    const float* wqr = (const float*)d_in[1];
    const float* wqi = (const float*)d_in[2];
    const float* wor = (const float*)d_in[3];
    const float* woi = (const float*)d_in[4];
    const float* w1  = (const float*)d_in[5];
    const float* b1  = (const float*)d_in[6];
    const float* w2  = (const float*)d_in[7];
    const int* nsy   = (const int*)d_in[9];
    float* out = (float*)d_out;

    k_modes_bias<<<MODE_BLOCKS + 16, 256>>>(seq, w1, b1, w2, nsy);
    k_qkv_mix<<<dim3(64, 6), 256>>>(wqr, wqi);
    k_attn<<<dim3(Bn * NH, 8), 128>>>();
    k_out_synth<<<dim3(256, 2), 256>>>(wor, woi, out);
}